// round 1
// baseline (speedup 1.0000x reference)
#include <cuda_runtime.h>
#include <math.h>

#define D_MODEL 1024
#define NHEADS  16
#define DK      64
#define SEQ     2048
#define BATCH   2
#define MTOT    (BATCH*SEQ)

// ---- device scratch (no cudaMalloc allowed) ----
__device__ float g_Q[(size_t)BATCH*NHEADS*SEQ*DK];
__device__ float g_K[(size_t)BATCH*NHEADS*SEQ*DK];
__device__ float g_V[(size_t)BATCH*NHEADS*SEQ*DK];
__device__ float g_A[(size_t)BATCH*SEQ*D_MODEL];
__device__ float g_cos[SEQ*(DK/2)];
__device__ float g_sin[SEQ*(DK/2)];

// ---------------- RoPE table (double precision, tiny) ----------------
__global__ void rope_table_kernel() {
    int i = blockIdx.x*blockDim.x + threadIdx.x;
    if (i >= SEQ*(DK/2)) return;
    int s = i / (DK/2);
    int j = i % (DK/2);
    double freq = pow(10000.0, -(double)(2*j)/(double)DK);
    double ang  = (double)s * freq;
    g_cos[i] = (float)cos(ang);
    g_sin[i] = (float)sin(ang);
}

// ---------------- fused QKV GEMM + RoPE epilogue ----------------
// out[m,n] = sum_k x[m,k] * W[n,k];  64x64 tile, BK=16, 256 thr, 4x4 micro-tile
__global__ __launch_bounds__(256) void qkv_gemm_kernel(
    const float* __restrict__ x,
    const float* __restrict__ Wq,
    const float* __restrict__ Wk,
    const float* __restrict__ Wv)
{
    const int z = blockIdx.z;   // 0=Q 1=K 2=V
    const float* __restrict__ W = (z==0) ? Wq : ((z==1) ? Wk : Wv);
    __shared__ float As[16][65];
    __shared__ float Bs[16][65];
    const int tid = threadIdx.x;
    const int tx = tid & 15, ty = tid >> 4;
    const int m0 = blockIdx.y * 64;
    const int n0 = blockIdx.x * 64;
    const int lr = tid >> 2;           // 0..63
    const int lc = (tid & 3) << 2;     // 0,4,8,12
    float c[4][4] = {};

    for (int k0 = 0; k0 < D_MODEL; k0 += 16) {
        float4 a = *(const float4*)(x + (size_t)(m0+lr)*D_MODEL + k0 + lc);
        float4 b = *(const float4*)(W + (size_t)(n0+lr)*D_MODEL + k0 + lc);
        As[lc+0][lr]=a.x; As[lc+1][lr]=a.y; As[lc+2][lr]=a.z; As[lc+3][lr]=a.w;
        Bs[lc+0][lr]=b.x; Bs[lc+1][lr]=b.y; Bs[lc+2][lr]=b.z; Bs[lc+3][lr]=b.w;
        __syncthreads();
        #pragma unroll
        for (int kk = 0; kk < 16; kk++) {
            float ra[4], rb[4];
            #pragma unroll
            for (int i = 0; i < 4; i++) ra[i] = As[kk][ty*4+i];
            #pragma unroll
            for (int j = 0; j < 4; j++) rb[j] = Bs[kk][tx*4+j];
            #pragma unroll
            for (int i = 0; i < 4; i++)
                #pragma unroll
                for (int j = 0; j < 4; j++)
                    c[i][j] = fmaf(ra[i], rb[j], c[i][j]);
        }
        __syncthreads();
    }

    if (z < 2) {
        float* out = (z==0) ? g_Q : g_K;
        #pragma unroll
        for (int i = 0; i < 4; i++) {
            int m = m0 + ty*4 + i;
            int b = m / SEQ, s = m % SEQ;
            #pragma unroll
            for (int j = 0; j < 4; j += 2) {
                int n = n0 + tx*4 + j;
                int h = n >> 6, d = n & 63;
                float cv = g_cos[s*(DK/2) + (d>>1)];
                float sv = g_sin[s*(DK/2) + (d>>1)];
                float x1 = c[i][j], x2 = c[i][j+1];
                size_t base = (((size_t)(b*NHEADS+h))*SEQ + s)*DK + d;
                out[base]   = cv*x1 - sv*x2;
                out[base+1] = sv*x1 + cv*x2;
            }
        }
    } else {
        #pragma unroll
        for (int i = 0; i < 4; i++) {
            int m = m0 + ty*4 + i;
            int b = m / SEQ, s = m % SEQ;
            #pragma unroll
            for (int j = 0; j < 4; j++) {
                int n = n0 + tx*4 + j;
                int h = n >> 6, d = n & 63;
                g_V[(((size_t)(b*NHEADS+h))*SEQ + s)*DK + d] = c[i][j];
            }
        }
    }
}

// ---------------- flash attention (causal, fp32) ----------------
// 64 queries/block, 256 threads, 4x4 micro-tiles, online softmax.
__global__ __launch_bounds__(256) void flash_kernel()
{
    extern __shared__ float sm[];
    float (*Qs)[65] = (float(*)[65])(sm);
    float (*Ks)[65] = (float(*)[65])(sm + 64*65);
    float (*Vs)[65] = (float(*)[65])(sm + 2*64*65);
    float (*Ps)[65] = (float(*)[65])(sm + 3*64*65);

    const int tid = threadIdx.x;
    const int tx = tid & 15, ty = tid >> 4;
    const int qt = blockIdx.x;
    const int bh = blockIdx.y;          // = b*16 + h
    const int b  = bh >> 4, h = bh & 15;

    const float* __restrict__ Qg = g_Q + (size_t)bh*SEQ*DK;
    const float* __restrict__ Kg = g_K + (size_t)bh*SEQ*DK;
    const float* __restrict__ Vg = g_V + (size_t)bh*SEQ*DK;

    for (int idx = tid; idx < 64*16; idx += 256) {
        int r = idx >> 4, c4 = (idx & 15) << 2;
        float4 v = *(const float4*)(Qg + (size_t)(qt*64 + r)*DK + c4);
        Qs[r][c4]=v.x; Qs[r][c4+1]=v.y; Qs[r][c4+2]=v.z; Qs[r][c4+3]=v.w;
    }

    float o[4][4] = {};
    float m_i[4], l_i[4];
    #pragma unroll
    for (int i = 0; i < 4; i++) { m_i[i] = -1e30f; l_i[i] = 0.f; }

    for (int kt = 0; kt <= qt; kt++) {
        __syncthreads();   // protect Ks/Vs/Ps reuse from previous iter (and Qs first iter)
        for (int idx = tid; idx < 64*16; idx += 256) {
            int r = idx >> 4, c4 = (idx & 15) << 2;
            float4 kv = *(const float4*)(Kg + (size_t)(kt*64 + r)*DK + c4);
            Ks[r][c4]=kv.x; Ks[r][c4+1]=kv.y; Ks[r][c4+2]=kv.z; Ks[r][c4+3]=kv.w;
            float4 vv = *(const float4*)(Vg + (size_t)(kt*64 + r)*DK + c4);
            Vs[r][c4]=vv.x; Vs[r][c4+1]=vv.y; Vs[r][c4+2]=vv.z; Vs[r][c4+3]=vv.w;
        }
        __syncthreads();

        float s[4][4] = {};
        #pragma unroll 8
        for (int d = 0; d < 64; d++) {
            float rq[4], rk[4];
            #pragma unroll
            for (int i = 0; i < 4; i++) rq[i] = Qs[ty*4+i][d];
            #pragma unroll
            for (int j = 0; j < 4; j++) rk[j] = Ks[tx*4+j][d];
            #pragma unroll
            for (int i = 0; i < 4; i++)
                #pragma unroll
                for (int j = 0; j < 4; j++)
                    s[i][j] = fmaf(rq[i], rk[j], s[i][j]);
        }

        const float scale = 0.125f;  // 1/sqrt(64)
        #pragma unroll
        for (int i = 0; i < 4; i++) {
            int qi = qt*64 + ty*4 + i;
            #pragma unroll
            for (int j = 0; j < 4; j++) {
                int kj = kt*64 + tx*4 + j;
                s[i][j] = (kj <= qi) ? s[i][j]*scale : -1e30f;
            }
        }

        #pragma unroll
        for (int i = 0; i < 4; i++) {
            float mx = fmaxf(fmaxf(s[i][0],s[i][1]), fmaxf(s[i][2],s[i][3]));
            #pragma unroll
            for (int off = 8; off >= 1; off >>= 1)
                mx = fmaxf(mx, __shfl_xor_sync(0xffffffffu, mx, off, 16));
            float m_new = fmaxf(m_i[i], mx);
            float p[4];
            float rs = 0.f;
            #pragma unroll
            for (int j = 0; j < 4; j++) { p[j] = __expf(s[i][j] - m_new); rs += p[j]; }
            #pragma unroll
            for (int off = 8; off >= 1; off >>= 1)
                rs += __shfl_xor_sync(0xffffffffu, rs, off, 16);
            float corr = __expf(m_i[i] - m_new);
            l_i[i] = l_i[i]*corr + rs;
            m_i[i] = m_new;
            #pragma unroll
            for (int j = 0; j < 4; j++) {
                o[i][j] *= corr;
                Ps[ty*4+i][tx*4+j] = p[j];
            }
        }
        __syncthreads();

        #pragma unroll 8
        for (int k = 0; k < 64; k++) {
            float rp[4], rv[4];
            #pragma unroll
            for (int i = 0; i < 4; i++) rp[i] = Ps[ty*4+i][k];
            #pragma unroll
            for (int j = 0; j < 4; j++) rv[j] = Vs[k][tx*4+j];
            #pragma unroll
            for (int i = 0; i < 4; i++)
                #pragma unroll
                for (int j = 0; j < 4; j++)
                    o[i][j] = fmaf(rp[i], rv[j], o[i][j]);
        }
    }

    // write to [B, S, H, DK] (== [B,S,D_MODEL] row-major for the out-projection)
    #pragma unroll
    for (int i = 0; i < 4; i++) {
        float inv = 1.0f / l_i[i];
        int s_idx = qt*64 + ty*4 + i;
        #pragma unroll
        for (int j = 0; j < 4; j++)
            g_A[(((size_t)b*SEQ + s_idx)*NHEADS + h)*DK + tx*4 + j] = o[i][j]*inv;
    }
}

// ---------------- output projection ----------------
__global__ __launch_bounds__(256) void out_gemm_kernel(
    const float* __restrict__ Wo, float* __restrict__ out)
{
    __shared__ float As[16][65];
    __shared__ float Bs[16][65];
    const int tid = threadIdx.x;
    const int tx = tid & 15, ty = tid >> 4;
    const int m0 = blockIdx.y * 64;
    const int n0 = blockIdx.x * 64;
    const int lr = tid >> 2;
    const int lc = (tid & 3) << 2;
    float c[4][4] = {};

    for (int k0 = 0; k0 < D_MODEL; k0 += 16) {
        float4 a = *(const float4*)(g_A + (size_t)(m0+lr)*D_MODEL + k0 + lc);
        float4 b = *(const float4*)(Wo  + (size_t)(n0+lr)*D_MODEL + k0 + lc);
        As[lc+0][lr]=a.x; As[lc+1][lr]=a.y; As[lc+2][lr]=a.z; As[lc+3][lr]=a.w;
        Bs[lc+0][lr]=b.x; Bs[lc+1][lr]=b.y; Bs[lc+2][lr]=b.z; Bs[lc+3][lr]=b.w;
        __syncthreads();
        #pragma unroll
        for (int kk = 0; kk < 16; kk++) {
            float ra[4], rb[4];
            #pragma unroll
            for (int i = 0; i < 4; i++) ra[i] = As[kk][ty*4+i];
            #pragma unroll
            for (int j = 0; j < 4; j++) rb[j] = Bs[kk][tx*4+j];
            #pragma unroll
            for (int i = 0; i < 4; i++)
                #pragma unroll
                for (int j = 0; j < 4; j++)
                    c[i][j] = fmaf(ra[i], rb[j], c[i][j]);
        }
        __syncthreads();
    }
    #pragma unroll
    for (int i = 0; i < 4; i++) {
        int m = m0 + ty*4 + i;
        #pragma unroll
        for (int j = 0; j < 4; j++) {
            int n = n0 + tx*4 + j;
            out[(size_t)m*D_MODEL + n] = c[i][j];
        }
    }
}

// ---------------- launch ----------------
extern "C" void kernel_launch(void* const* d_in, const int* in_sizes, int n_in,
                              void* d_out, int out_size)
{
    const float* x  = (const float*)d_in[0];
    const float* Wq = (const float*)d_in[1];
    const float* Wk = (const float*)d_in[2];
    const float* Wv = (const float*)d_in[3];
    const float* Wo = (const float*)d_in[4];
    float* out = (float*)d_out;

    const int flash_smem = 4*64*65*sizeof(float);   // 66560 B
    cudaFuncSetAttribute(flash_kernel, cudaFuncAttributeMaxDynamicSharedMemorySize, flash_smem);

    rope_table_kernel<<<(SEQ*(DK/2) + 255)/256, 256>>>();

    dim3 g1(D_MODEL/64, MTOT/64, 3);
    qkv_gemm_kernel<<<g1, 256>>>(x, Wq, Wk, Wv);

    dim3 g2(SEQ/64, BATCH*NHEADS);
    flash_kernel<<<g2, 256, flash_smem>>>();

    dim3 g3(D_MODEL/64, MTOT/64, 1);
    out_gemm_kernel<<<g3, 256>>>(Wo, out);
}

// round 2
// speedup vs baseline: 1.3095x; 1.3095x over previous
#include <cuda_runtime.h>
#include <math.h>

#define D_MODEL 1024
#define NHEADS  16
#define DK      64
#define SEQ     2048
#define BATCH   2
#define MTOT    (BATCH*SEQ)

// ---- device scratch (no cudaMalloc allowed) ----
__device__ float g_Q[(size_t)BATCH*NHEADS*SEQ*DK];
__device__ float g_K[(size_t)BATCH*NHEADS*SEQ*DK];
__device__ float g_V[(size_t)BATCH*NHEADS*SEQ*DK];
__device__ float g_A[(size_t)BATCH*SEQ*D_MODEL];
__device__ float g_cos[SEQ*(DK/2)];
__device__ float g_sin[SEQ*(DK/2)];

// ---------------- RoPE table (double precision, tiny) ----------------
__global__ void rope_table_kernel() {
    int i = blockIdx.x*blockDim.x + threadIdx.x;
    if (i >= SEQ*(DK/2)) return;
    int s = i / (DK/2);
    int j = i % (DK/2);
    double freq = pow(10000.0, -(double)(2*j)/(double)DK);
    double ang  = (double)s * freq;
    g_cos[i] = (float)cos(ang);
    g_sin[i] = (float)sin(ang);
}

// fast exp2 on fma/alu pipes (avoids MUFU throughput wall)
__device__ __forceinline__ float exp2f_fast(float x) {
    x = fmaxf(x, -125.0f);
    float t = x + 12582912.0f;              // round-to-nearest-int via magic
    float f = x - (t - 12582912.0f);        // f in [-0.5, 0.5]
    int   e = __float_as_int(t) << 23;      // 2^n exponent bits (mod 2^32 trick)
    float p = 1.5402387e-4f;
    p = fmaf(p, f, 1.3333558e-3f);
    p = fmaf(p, f, 9.6181291e-3f);
    p = fmaf(p, f, 5.5504109e-2f);
    p = fmaf(p, f, 2.4022651e-1f);
    p = fmaf(p, f, 6.9314718e-1f);
    p = fmaf(p, f, 1.0f);
    return __int_as_float(__float_as_int(p) + e);
}

// ---------------- fused QKV GEMM + RoPE epilogue ----------------
// 128x128 tile, BK=16, 256 threads, 8x8 micro-tile.
__global__ __launch_bounds__(256,2) void qkv_gemm_kernel(
    const float* __restrict__ x,
    const float* __restrict__ Wq,
    const float* __restrict__ Wk,
    const float* __restrict__ Wv)
{
    __shared__ float As[16][132];
    __shared__ float Bs[16][132];
    const int z = blockIdx.z;   // 0=Q 1=K 2=V
    const float* __restrict__ W = (z==0) ? Wq : ((z==1) ? Wk : Wv);
    const int tid = threadIdx.x;
    const int tx = tid & 15, ty = tid >> 4;
    const int m0 = blockIdx.y * 128;
    const int n0 = blockIdx.x * 128;
    const int r  = tid >> 2;            // 0..63
    const int c4 = (tid & 3) << 2;      // 0,4,8,12

    const float* Aptr = x + (size_t)(m0 + r)*D_MODEL + c4;
    const float* Bptr = W + (size_t)(n0 + r)*D_MODEL + c4;

    float4 a0 = *(const float4*)(Aptr);
    float4 a1 = *(const float4*)(Aptr + 64*D_MODEL);
    float4 b0 = *(const float4*)(Bptr);
    float4 b1 = *(const float4*)(Bptr + 64*D_MODEL);

    float c[8][8] = {};

    for (int k0 = 0; k0 < D_MODEL; k0 += 16) {
        As[c4+0][r]=a0.x; As[c4+1][r]=a0.y; As[c4+2][r]=a0.z; As[c4+3][r]=a0.w;
        As[c4+0][r+64]=a1.x; As[c4+1][r+64]=a1.y; As[c4+2][r+64]=a1.z; As[c4+3][r+64]=a1.w;
        Bs[c4+0][r]=b0.x; Bs[c4+1][r]=b0.y; Bs[c4+2][r]=b0.z; Bs[c4+3][r]=b0.w;
        Bs[c4+0][r+64]=b1.x; Bs[c4+1][r+64]=b1.y; Bs[c4+2][r+64]=b1.z; Bs[c4+3][r+64]=b1.w;
        __syncthreads();
        if (k0 + 16 < D_MODEL) {
            a0 = *(const float4*)(Aptr + k0 + 16);
            a1 = *(const float4*)(Aptr + 64*D_MODEL + k0 + 16);
            b0 = *(const float4*)(Bptr + k0 + 16);
            b1 = *(const float4*)(Bptr + 64*D_MODEL + k0 + 16);
        }
        #pragma unroll
        for (int kk = 0; kk < 16; kk++) {
            float ra[8], rb[8];
            *(float4*)(ra)   = *(const float4*)&As[kk][ty*8];
            *(float4*)(ra+4) = *(const float4*)&As[kk][ty*8+4];
            *(float4*)(rb)   = *(const float4*)&Bs[kk][tx*8];
            *(float4*)(rb+4) = *(const float4*)&Bs[kk][tx*8+4];
            #pragma unroll
            for (int i = 0; i < 8; i++)
                #pragma unroll
                for (int j = 0; j < 8; j++)
                    c[i][j] = fmaf(ra[i], rb[j], c[i][j]);
        }
        __syncthreads();
    }

    const int n_base = n0 + tx*8;
    const int h = n_base >> 6;
    const int d = n_base & 63;
    if (z < 2) {
        float* out = (z==0) ? g_Q : g_K;
        #pragma unroll
        for (int i = 0; i < 8; i++) {
            int m = m0 + ty*8 + i;
            int b = m >> 11, s = m & (SEQ-1);
            const float* cs = g_cos + s*(DK/2) + (d>>1);
            const float* sn = g_sin + s*(DK/2) + (d>>1);
            float o[8];
            #pragma unroll
            for (int j = 0; j < 8; j += 2) {
                float cv = cs[j>>1], sv = sn[j>>1];
                o[j]   = cv*c[i][j] - sv*c[i][j+1];
                o[j+1] = sv*c[i][j] + cv*c[i][j+1];
            }
            float* dst = out + (((size_t)(b*NHEADS+h))*SEQ + s)*DK + d;
            *(float4*)(dst)   = make_float4(o[0],o[1],o[2],o[3]);
            *(float4*)(dst+4) = make_float4(o[4],o[5],o[6],o[7]);
        }
    } else {
        #pragma unroll
        for (int i = 0; i < 8; i++) {
            int m = m0 + ty*8 + i;
            int b = m >> 11, s = m & (SEQ-1);
            float* dst = g_V + (((size_t)(b*NHEADS+h))*SEQ + s)*DK + d;
            *(float4*)(dst)   = make_float4(c[i][0],c[i][1],c[i][2],c[i][3]);
            *(float4*)(dst+4) = make_float4(c[i][4],c[i][5],c[i][6],c[i][7]);
        }
    }
}

// ---------------- flash attention (causal, fp32) ----------------
// BM=128 queries, BN=64 keys, 256 threads, 8x4 micro-tile, software exp2.
__global__ __launch_bounds__(256,2) void flash_kernel()
{
    extern __shared__ float sm[];
    float (*Qs)[132] = (float(*)[132])(sm);                     // [d=64][row 128+pad]
    float (*Ks)[68]  = (float(*)[68]) (sm + 64*132);            // [d=64][col 64+pad]
    float (*Vs)[68]  = (float(*)[68]) (sm + 64*132 + 64*68);    // [k=64][col 64+pad]
    float (*Ps)[132] = (float(*)[132])(sm + 64*132 + 2*64*68);  // [k=64][row 128+pad]

    const int tid = threadIdx.x;
    const int tx = tid & 15, ty = tid >> 4;
    const int qt = gridDim.x - 1 - blockIdx.x;   // long blocks first
    const int bh = blockIdx.y;
    const int b  = bh >> 4, h = bh & 15;

    const float* __restrict__ Qg = g_Q + (size_t)bh*SEQ*DK;
    const float* __restrict__ Kg = g_K + (size_t)bh*SEQ*DK;
    const float* __restrict__ Vg = g_V + (size_t)bh*SEQ*DK;

    #pragma unroll
    for (int it = 0; it < 8; it++) {
        int idx = tid + it*256;
        int rq = idx >> 4, c4 = (idx & 15) << 2;
        float4 v = *(const float4*)(Qg + (size_t)(qt*128 + rq)*DK + c4);
        Qs[c4+0][rq]=v.x; Qs[c4+1][rq]=v.y; Qs[c4+2][rq]=v.z; Qs[c4+3][rq]=v.w;
    }

    float o[8][4] = {};
    float m_i[8], l_i[8];
    #pragma unroll
    for (int i = 0; i < 8; i++) { m_i[i] = -1e30f; l_i[i] = 0.f; }

    const float SC = 0.18033688011112042f;  // log2(e)/sqrt(64)
    const int ktmax = 2*qt + 1;

    for (int kt = 0; kt <= ktmax; kt++) {
        __syncthreads();
        #pragma unroll
        for (int it = 0; it < 4; it++) {
            int idx = tid + it*256;
            int rk = idx >> 4, c4 = (idx & 15) << 2;
            float4 kv = *(const float4*)(Kg + (size_t)(kt*64 + rk)*DK + c4);
            Ks[c4+0][rk]=kv.x; Ks[c4+1][rk]=kv.y; Ks[c4+2][rk]=kv.z; Ks[c4+3][rk]=kv.w;
            float4 vv = *(const float4*)(Vg + (size_t)(kt*64 + rk)*DK + c4);
            *(float4*)&Vs[rk][c4] = vv;
        }
        __syncthreads();

        float s_[8][4] = {};
        #pragma unroll 8
        for (int d = 0; d < 64; d++) {
            float rq[8], rk[4];
            *(float4*)(rq)   = *(const float4*)&Qs[d][ty*8];
            *(float4*)(rq+4) = *(const float4*)&Qs[d][ty*8+4];
            *(float4*)(rk)   = *(const float4*)&Ks[d][tx*4];
            #pragma unroll
            for (int i = 0; i < 8; i++)
                #pragma unroll
                for (int j = 0; j < 4; j++)
                    s_[i][j] = fmaf(rq[i], rk[j], s_[i][j]);
        }

        if (kt >= 2*qt) {   // diagonal tile: apply causal mask
            #pragma unroll
            for (int i = 0; i < 8; i++) {
                int qi = qt*128 + ty*8 + i;
                #pragma unroll
                for (int j = 0; j < 4; j++) {
                    int kj = kt*64 + tx*4 + j;
                    s_[i][j] = (kj <= qi) ? s_[i][j]*SC : -1e30f;
                }
            }
        } else {
            #pragma unroll
            for (int i = 0; i < 8; i++)
                #pragma unroll
                for (int j = 0; j < 4; j++)
                    s_[i][j] *= SC;
        }

        #pragma unroll
        for (int i = 0; i < 8; i++) {
            float mx = fmaxf(fmaxf(s_[i][0],s_[i][1]), fmaxf(s_[i][2],s_[i][3]));
            #pragma unroll
            for (int off = 8; off >= 1; off >>= 1)
                mx = fmaxf(mx, __shfl_xor_sync(0xffffffffu, mx, off, 16));
            float mnew = fmaxf(m_i[i], mx);
            float p[4], rs = 0.f;
            #pragma unroll
            for (int j = 0; j < 4; j++) { p[j] = exp2f_fast(s_[i][j] - mnew); rs += p[j]; }
            #pragma unroll
            for (int off = 8; off >= 1; off >>= 1)
                rs += __shfl_xor_sync(0xffffffffu, rs, off, 16);
            float corr = exp2f_fast(m_i[i] - mnew);
            l_i[i] = l_i[i]*corr + rs;
            m_i[i] = mnew;
            #pragma unroll
            for (int j = 0; j < 4; j++) {
                o[i][j] *= corr;
                Ps[tx*4+j][ty*8+i] = p[j];
            }
        }
        __syncthreads();

        #pragma unroll 8
        for (int k = 0; k < 64; k++) {
            float rp[8], rv[4];
            *(float4*)(rp)   = *(const float4*)&Ps[k][ty*8];
            *(float4*)(rp+4) = *(const float4*)&Ps[k][ty*8+4];
            *(float4*)(rv)   = *(const float4*)&Vs[k][tx*4];
            #pragma unroll
            for (int i = 0; i < 8; i++)
                #pragma unroll
                for (int j = 0; j < 4; j++)
                    o[i][j] = fmaf(rp[i], rv[j], o[i][j]);
        }
    }

    #pragma unroll
    for (int i = 0; i < 8; i++) {
        float inv = 1.0f / l_i[i];
        int s_idx = qt*128 + ty*8 + i;
        float4 val = make_float4(o[i][0]*inv, o[i][1]*inv, o[i][2]*inv, o[i][3]*inv);
        *(float4*)(g_A + ((size_t)b*SEQ + s_idx)*D_MODEL + h*DK + tx*4) = val;
    }
}

// ---------------- output projection (128x128, 8x8 micro) ----------------
__global__ __launch_bounds__(256,2) void out_gemm_kernel(
    const float* __restrict__ Wo, float* __restrict__ out)
{
    __shared__ float As[16][132];
    __shared__ float Bs[16][132];
    const int tid = threadIdx.x;
    const int tx = tid & 15, ty = tid >> 4;
    const int m0 = blockIdx.y * 128;
    const int n0 = blockIdx.x * 128;
    const int r  = tid >> 2;
    const int c4 = (tid & 3) << 2;

    const float* Aptr = g_A + (size_t)(m0 + r)*D_MODEL + c4;
    const float* Bptr = Wo  + (size_t)(n0 + r)*D_MODEL + c4;

    float4 a0 = *(const float4*)(Aptr);
    float4 a1 = *(const float4*)(Aptr + 64*D_MODEL);
    float4 b0 = *(const float4*)(Bptr);
    float4 b1 = *(const float4*)(Bptr + 64*D_MODEL);

    float c[8][8] = {};

    for (int k0 = 0; k0 < D_MODEL; k0 += 16) {
        As[c4+0][r]=a0.x; As[c4+1][r]=a0.y; As[c4+2][r]=a0.z; As[c4+3][r]=a0.w;
        As[c4+0][r+64]=a1.x; As[c4+1][r+64]=a1.y; As[c4+2][r+64]=a1.z; As[c4+3][r+64]=a1.w;
        Bs[c4+0][r]=b0.x; Bs[c4+1][r]=b0.y; Bs[c4+2][r]=b0.z; Bs[c4+3][r]=b0.w;
        Bs[c4+0][r+64]=b1.x; Bs[c4+1][r+64]=b1.y; Bs[c4+2][r+64]=b1.z; Bs[c4+3][r+64]=b1.w;
        __syncthreads();
        if (k0 + 16 < D_MODEL) {
            a0 = *(const float4*)(Aptr + k0 + 16);
            a1 = *(const float4*)(Aptr + 64*D_MODEL + k0 + 16);
            b0 = *(const float4*)(Bptr + k0 + 16);
            b1 = *(const float4*)(Bptr + 64*D_MODEL + k0 + 16);
        }
        #pragma unroll
        for (int kk = 0; kk < 16; kk++) {
            float ra[8], rb[8];
            *(float4*)(ra)   = *(const float4*)&As[kk][ty*8];
            *(float4*)(ra+4) = *(const float4*)&As[kk][ty*8+4];
            *(float4*)(rb)   = *(const float4*)&Bs[kk][tx*8];
            *(float4*)(rb+4) = *(const float4*)&Bs[kk][tx*8+4];
            #pragma unroll
            for (int i = 0; i < 8; i++)
                #pragma unroll
                for (int j = 0; j < 8; j++)
                    c[i][j] = fmaf(ra[i], rb[j], c[i][j]);
        }
        __syncthreads();
    }
    #pragma unroll
    for (int i = 0; i < 8; i++) {
        int m = m0 + ty*8 + i;
        float* dst = out + (size_t)m*D_MODEL + n0 + tx*8;
        *(float4*)(dst)   = make_float4(c[i][0],c[i][1],c[i][2],c[i][3]);
        *(float4*)(dst+4) = make_float4(c[i][4],c[i][5],c[i][6],c[i][7]);
    }
}

// ---------------- launch ----------------
extern "C" void kernel_launch(void* const* d_in, const int* in_sizes, int n_in,
                              void* d_out, int out_size)
{
    const float* x  = (const float*)d_in[0];
    const float* Wq = (const float*)d_in[1];
    const float* Wk = (const float*)d_in[2];
    const float* Wv = (const float*)d_in[3];
    const float* Wo = (const float*)d_in[4];
    float* out = (float*)d_out;

    const int flash_smem = (64*132 + 2*64*68 + 64*132) * sizeof(float);  // 102400 B
    cudaFuncSetAttribute(flash_kernel, cudaFuncAttributeMaxDynamicSharedMemorySize, flash_smem);

    rope_table_kernel<<<(SEQ*(DK/2) + 255)/256, 256>>>();

    dim3 g1(D_MODEL/128, MTOT/128, 3);
    qkv_gemm_kernel<<<g1, 256>>>(x, Wq, Wk, Wv);

    dim3 g2(SEQ/128, BATCH*NHEADS);
    flash_kernel<<<g2, 256, flash_smem>>>();

    dim3 g3(D_MODEL/128, MTOT/128, 1);
    out_gemm_kernel<<<g3, 256>>>(Wo, out);
}